// round 2
// baseline (speedup 1.0000x reference)
#include <cuda_runtime.h>
#include <cuda_bf16.h>
#include <stdint.h>

#define NNODES 100000
#define FDIM   64

// Scratch (static device globals — no allocation allowed in kernel_launch)
__device__ __align__(16) float g_h[(size_t)NNODES * FDIM];    // 25.6 MB
__device__ __align__(16) float g_agg[(size_t)NNODES * FDIM];  // 25.6 MB
__device__ float g_deg[NNODES];
__device__ float g_dinv[NNODES];

// ---------------------------------------------------------------------------
// vectorized reduction: red.global.add.v4.f32 (sm_90+)
// ---------------------------------------------------------------------------
__device__ __forceinline__ void red_add_v4(float* addr, float4 v) {
    asm volatile("red.global.add.v4.f32 [%0], {%1, %2, %3, %4};"
                 :: "l"(addr), "f"(v.x), "f"(v.y), "f"(v.z), "f"(v.w)
                 : "memory");
}

// ---------------------------------------------------------------------------
// zero scratch: g_agg, g_deg, and d_out (layer-2 agg buffer)
// ---------------------------------------------------------------------------
__global__ void zero_kernel(float* __restrict__ out) {
    const long long total4 = (long long)NNODES * FDIM / 4;  // float4 count
    long long stride = (long long)gridDim.x * blockDim.x;
    float4 z = make_float4(0.f, 0.f, 0.f, 0.f);
    for (long long i = (long long)blockIdx.x * blockDim.x + threadIdx.x;
         i < total4; i += stride) {
        reinterpret_cast<float4*>(g_agg)[i] = z;
        reinterpret_cast<float4*>(out)[i]   = z;
    }
    for (long long i = (long long)blockIdx.x * blockDim.x + threadIdx.x;
         i < NNODES; i += stride) {
        g_deg[i] = 0.0f;
    }
}

// ---------------------------------------------------------------------------
// degree: deg[dst] += 1 per edge (exact in fp32: counts < 2^24)
// edge_index is int32 (JAX x64 disabled): layout [2, E] row-major.
// ---------------------------------------------------------------------------
__global__ void deg_kernel(const int* __restrict__ ei, long long E) {
    long long stride = (long long)gridDim.x * blockDim.x;
    for (long long e = (long long)blockIdx.x * blockDim.x + threadIdx.x;
         e < E; e += stride) {
        int d = ei[E + e];
        atomicAdd(&g_deg[d], 1.0f);
    }
}

__global__ void dinv_kernel() {
    long long stride = (long long)gridDim.x * blockDim.x;
    for (long long i = (long long)blockIdx.x * blockDim.x + threadIdx.x;
         i < NNODES; i += stride) {
        g_dinv[i] = rsqrtf(g_deg[i] + 1.0f);
    }
}

// ---------------------------------------------------------------------------
// GEMM: C[n, 64] = A[n, 64] @ W[64, 64], fp32.
// Block = 256 threads handles 64 rows. 4 threads per row, 16 cols each.
// ---------------------------------------------------------------------------
__global__ __launch_bounds__(256) void gemm64_kernel(
    const float* __restrict__ A, const float* __restrict__ W,
    float* __restrict__ C, int n_rows)
{
    __shared__ float sW[64 * 64];       // 16 KB
    __shared__ float sA[64 * 65];       // padded to kill bank conflicts

    const int tid  = threadIdx.x;
    const int row0 = blockIdx.x * 64;

    // load W (whole 64x64, coalesced float4)
    for (int i = tid; i < 64 * 64 / 4; i += 256)
        reinterpret_cast<float4*>(sW)[i] =
            reinterpret_cast<const float4*>(W)[i];

    // load A tile: 64 rows x 16 float4 = 1024 float4
    for (int i = tid; i < 1024; i += 256) {
        int r  = i >> 4;
        int c4 = i & 15;
        float4 v = make_float4(0.f, 0.f, 0.f, 0.f);
        if (row0 + r < n_rows)
            v = reinterpret_cast<const float4*>(
                    A + (size_t)(row0 + r) * FDIM)[c4];
        float* dst = &sA[r * 65 + c4 * 4];
        dst[0] = v.x; dst[1] = v.y; dst[2] = v.z; dst[3] = v.w;
    }
    __syncthreads();

    const int r  = tid >> 2;         // local row 0..63
    const int cg = (tid & 3) * 16;   // col base 0/16/32/48

    float acc[16];
#pragma unroll
    for (int i = 0; i < 16; i++) acc[i] = 0.f;

#pragma unroll 4
    for (int k = 0; k < 64; k++) {
        float a = sA[r * 65 + k];
        const float4* wr = reinterpret_cast<const float4*>(sW + k * 64 + cg);
#pragma unroll
        for (int i = 0; i < 4; i++) {
            float4 w = wr[i];
            acc[4 * i + 0] += a * w.x;
            acc[4 * i + 1] += a * w.y;
            acc[4 * i + 2] += a * w.z;
            acc[4 * i + 3] += a * w.w;
        }
    }

    if (row0 + r < n_rows) {
        float4* out = reinterpret_cast<float4*>(
            C + (size_t)(row0 + r) * FDIM + cg);
#pragma unroll
        for (int i = 0; i < 4; i++)
            out[i] = make_float4(acc[4 * i + 0], acc[4 * i + 1],
                                 acc[4 * i + 2], acc[4 * i + 3]);
    }
}

// ---------------------------------------------------------------------------
// Edge scatter: agg[dst] += h[src] * dinv[src] * dinv[dst]
// 16 lanes per edge, each lane owns one float4 of the 64-float row.
// ---------------------------------------------------------------------------
__global__ __launch_bounds__(256) void scatter_kernel(
    const int* __restrict__ ei, long long E,
    const float* __restrict__ h, float* __restrict__ agg)
{
    const long long nlane = E * 16;
    const long long stride = (long long)gridDim.x * blockDim.x;
    for (long long i = (long long)blockIdx.x * blockDim.x + threadIdx.x;
         i < nlane; i += stride) {
        long long e = i >> 4;
        int sub     = (int)(i & 15);
        long long s = ei[e];
        long long d = ei[E + e];
        float norm  = g_dinv[s] * g_dinv[d];
        float4 v = reinterpret_cast<const float4*>(h + s * FDIM)[sub];
        v.x *= norm; v.y *= norm; v.z *= norm; v.w *= norm;
        red_add_v4(agg + d * FDIM + sub * 4, v);
    }
}

// ---------------------------------------------------------------------------
// Finalize: agg = relu(agg + h * dinv^2 + b)   (in place on agg)
// ---------------------------------------------------------------------------
__global__ __launch_bounds__(256) void finalize_kernel(
    const float* __restrict__ h, float* __restrict__ agg,
    const float* __restrict__ b)
{
    const long long total4 = (long long)NNODES * (FDIM / 4);
    const long long stride = (long long)gridDim.x * blockDim.x;
    for (long long i = (long long)blockIdx.x * blockDim.x + threadIdx.x;
         i < total4; i += stride) {
        long long node = i >> 4;
        int c4         = (int)(i & 15);
        float di = g_dinv[node];
        float sl = di * di;
        float4 hv = reinterpret_cast<const float4*>(h)[i];
        float4 av = reinterpret_cast<float4*>(agg)[i];
        float4 bv = reinterpret_cast<const float4*>(b)[c4];
        av.x = fmaxf(av.x + hv.x * sl + bv.x, 0.f);
        av.y = fmaxf(av.y + hv.y * sl + bv.y, 0.f);
        av.z = fmaxf(av.z + hv.z * sl + bv.z, 0.f);
        av.w = fmaxf(av.w + hv.w * sl + bv.w, 0.f);
        reinterpret_cast<float4*>(agg)[i] = av;
    }
}

// ---------------------------------------------------------------------------
extern "C" void kernel_launch(void* const* d_in, const int* in_sizes, int n_in,
                              void* d_out, int out_size)
{
    const float* x  = (const float*)d_in[0];
    const int*   ei = (const int*)d_in[1];     // int32! (JAX x64 disabled)
    const float* W1 = (const float*)d_in[2];
    const float* b1 = (const float*)d_in[3];
    const float* W2 = (const float*)d_in[4];
    const float* b2 = (const float*)d_in[5];
    float* out = (float*)d_out;

    const long long E = (long long)in_sizes[1] / 2;

    float* g_h_ptr;   cudaGetSymbolAddress((void**)&g_h_ptr,   g_h);
    float* g_agg_ptr; cudaGetSymbolAddress((void**)&g_agg_ptr, g_agg);

    const int SMS = 148;
    dim3 blk(256);

    // zero agg, deg, and out (out doubles as layer-2 agg buffer)
    zero_kernel<<<SMS * 8, blk>>>(out);

    // degree + normalization
    deg_kernel<<<SMS * 8, blk>>>(ei, E);
    dinv_kernel<<<(NNODES + 255) / 256, blk>>>();

    const int gemm_grid = (NNODES + 63) / 64;
    const int scat_grid = SMS * 20;

    // ---- layer 1 ----
    gemm64_kernel<<<gemm_grid, blk>>>(x, W1, g_h_ptr, NNODES);
    scatter_kernel<<<scat_grid, blk>>>(ei, E, g_h_ptr, g_agg_ptr);
    finalize_kernel<<<SMS * 8, blk>>>(g_h_ptr, g_agg_ptr, b1);  // act -> g_agg

    // ---- layer 2 ----
    gemm64_kernel<<<gemm_grid, blk>>>(g_agg_ptr, W2, g_h_ptr, NNODES);
    scatter_kernel<<<scat_grid, blk>>>(ei, E, g_h_ptr, out);    // out was zeroed
    finalize_kernel<<<SMS * 8, blk>>>(g_h_ptr, out, b2);
}

// round 3
// speedup vs baseline: 1.2560x; 1.2560x over previous
#include <cuda_runtime.h>
#include <cuda_bf16.h>
#include <stdint.h>

#define NNODES 100000
#define FDIM   64

// Scratch (static device globals — no allocation allowed in kernel_launch)
__device__ __align__(16) float g_h[(size_t)NNODES * FDIM];    // 25.6 MB
__device__ __align__(16) float g_agg[(size_t)NNODES * FDIM];  // 25.6 MB
__device__ float g_deg[NNODES];
__device__ float g_dinv[NNODES];

// ---------------------------------------------------------------------------
__device__ __forceinline__ void red_add_v4(float* addr, float4 v) {
    asm volatile("red.global.add.v4.f32 [%0], {%1, %2, %3, %4};"
                 :: "l"(addr), "f"(v.x), "f"(v.y), "f"(v.z), "f"(v.w)
                 : "memory");
}

// ---------------------------------------------------------------------------
// zero scratch: g_agg, g_deg, and d_out (layer-2 agg buffer)
// ---------------------------------------------------------------------------
__global__ void zero_kernel(float* __restrict__ out) {
    const long long total4 = (long long)NNODES * FDIM / 4;
    long long stride = (long long)gridDim.x * blockDim.x;
    float4 z = make_float4(0.f, 0.f, 0.f, 0.f);
    for (long long i = (long long)blockIdx.x * blockDim.x + threadIdx.x;
         i < total4; i += stride) {
        reinterpret_cast<float4*>(g_agg)[i] = z;
        reinterpret_cast<float4*>(out)[i]   = z;
    }
    for (long long i = (long long)blockIdx.x * blockDim.x + threadIdx.x;
         i < NNODES; i += stride) {
        g_deg[i] = 0.0f;
    }
}

// ---------------------------------------------------------------------------
// degree: deg[dst] += 1 per edge (exact in fp32). edge_index int32, [2, E].
// ---------------------------------------------------------------------------
__global__ void deg_kernel(const int* __restrict__ ei, long long E) {
    long long stride = (long long)gridDim.x * blockDim.x;
    for (long long e = (long long)blockIdx.x * blockDim.x + threadIdx.x;
         e < E; e += stride) {
        atomicAdd(&g_deg[ei[E + e]], 1.0f);
    }
}

__global__ void dinv_kernel() {
    long long stride = (long long)gridDim.x * blockDim.x;
    for (long long i = (long long)blockIdx.x * blockDim.x + threadIdx.x;
         i < NNODES; i += stride) {
        g_dinv[i] = rsqrtf(g_deg[i] + 1.0f);
    }
}

// ---------------------------------------------------------------------------
// GEMM: C[n,64] = A[n,64] @ W[64,64], fp32.
// 256 threads / 128 rows per block. Each thread: 2 rows x 16 cols (32 acc).
// Per k: 2 scalar LDS + 4 LDS.128  -> 6 LDS per 32 FFMA (FMA-pipe bound).
// FUSED: A-element = relu(A + hprev*dinv^2 + bias)  (fuses layer-1 finalize).
// ---------------------------------------------------------------------------
template <bool FUSED>
__global__ __launch_bounds__(256) void gemm64_kernel(
    const float* __restrict__ A, const float* __restrict__ W,
    float* __restrict__ C, int n_rows,
    const float* __restrict__ hprev, const float* __restrict__ bias)
{
    extern __shared__ float smem[];
    float* sW = smem;                 // 64*64   = 4096 floats
    float* sA = smem + 64 * 64;       // 128*65  = 8320 floats (padded)

    const int tid  = threadIdx.x;
    const int row0 = blockIdx.x * 128;

    // W: 64x64, coalesced float4
    for (int i = tid; i < 1024; i += 256)
        reinterpret_cast<float4*>(sW)[i] =
            reinterpret_cast<const float4*>(W)[i];

    // A tile: 128 rows x 16 float4 (optionally fused activation)
    for (int i = tid; i < 2048; i += 256) {
        int r  = i >> 4;
        int c4 = i & 15;
        int row = row0 + r;
        float4 v = make_float4(0.f, 0.f, 0.f, 0.f);
        if (row < n_rows) {
            v = reinterpret_cast<const float4*>(A + (size_t)row * FDIM)[c4];
            if (FUSED) {
                float4 hv = reinterpret_cast<const float4*>(
                                hprev + (size_t)row * FDIM)[c4];
                float4 bv = reinterpret_cast<const float4*>(bias)[c4];
                float di = g_dinv[row];
                float sl = di * di;
                v.x = fmaxf(fmaf(hv.x, sl, v.x) + bv.x, 0.f);
                v.y = fmaxf(fmaf(hv.y, sl, v.y) + bv.y, 0.f);
                v.z = fmaxf(fmaf(hv.z, sl, v.z) + bv.z, 0.f);
                v.w = fmaxf(fmaf(hv.w, sl, v.w) + bv.w, 0.f);
            }
        }
        float* dst = &sA[r * 65 + c4 * 4];
        dst[0] = v.x; dst[1] = v.y; dst[2] = v.z; dst[3] = v.w;
    }
    __syncthreads();

    const int r0 = (tid >> 2) * 2;     // local row pair base: 0..126
    const int cg = (tid & 3) * 16;     // col base: 0/16/32/48

    float acc0[16], acc1[16];
#pragma unroll
    for (int i = 0; i < 16; i++) { acc0[i] = 0.f; acc1[i] = 0.f; }

#pragma unroll 8
    for (int k = 0; k < 64; k++) {
        float a0 = sA[r0 * 65 + k];
        float a1 = sA[(r0 + 1) * 65 + k];
        const float4* wr = reinterpret_cast<const float4*>(sW + k * 64 + cg);
#pragma unroll
        for (int i = 0; i < 4; i++) {
            float4 w = wr[i];
            acc0[4 * i + 0] += a0 * w.x;  acc1[4 * i + 0] += a1 * w.x;
            acc0[4 * i + 1] += a0 * w.y;  acc1[4 * i + 1] += a1 * w.y;
            acc0[4 * i + 2] += a0 * w.z;  acc1[4 * i + 2] += a1 * w.z;
            acc0[4 * i + 3] += a0 * w.w;  acc1[4 * i + 3] += a1 * w.w;
        }
    }

    if (row0 + r0 < n_rows) {
        float4* o0 = reinterpret_cast<float4*>(
            C + (size_t)(row0 + r0) * FDIM + cg);
#pragma unroll
        for (int i = 0; i < 4; i++)
            o0[i] = make_float4(acc0[4*i+0], acc0[4*i+1], acc0[4*i+2], acc0[4*i+3]);
    }
    if (row0 + r0 + 1 < n_rows) {
        float4* o1 = reinterpret_cast<float4*>(
            C + (size_t)(row0 + r0 + 1) * FDIM + cg);
#pragma unroll
        for (int i = 0; i < 4; i++)
            o1[i] = make_float4(acc1[4*i+0], acc1[4*i+1], acc1[4*i+2], acc1[4*i+3]);
    }
}

// ---------------------------------------------------------------------------
// Edge scatter: agg[dst] += h[src] * dinv[src] * dinv[dst]
// 16 lanes per edge, each lane owns one float4 of the 64-float row.
// ---------------------------------------------------------------------------
__global__ __launch_bounds__(256) void scatter_kernel(
    const int* __restrict__ ei, long long E,
    const float* __restrict__ h, float* __restrict__ agg)
{
    const long long nlane = E * 16;
    const long long stride = (long long)gridDim.x * blockDim.x;
    for (long long i = (long long)blockIdx.x * blockDim.x + threadIdx.x;
         i < nlane; i += stride) {
        long long e = i >> 4;
        int sub     = (int)(i & 15);
        long long s = ei[e];
        long long d = ei[E + e];
        float norm  = g_dinv[s] * g_dinv[d];
        float4 v = reinterpret_cast<const float4*>(h + s * FDIM)[sub];
        v.x *= norm; v.y *= norm; v.z *= norm; v.w *= norm;
        red_add_v4(agg + d * FDIM + sub * 4, v);
    }
}

// ---------------------------------------------------------------------------
// Finalize: agg = relu(agg + h * dinv^2 + b)   (in place on agg)
// ---------------------------------------------------------------------------
__global__ __launch_bounds__(256) void finalize_kernel(
    const float* __restrict__ h, float* __restrict__ agg,
    const float* __restrict__ b)
{
    const long long total4 = (long long)NNODES * (FDIM / 4);
    const long long stride = (long long)gridDim.x * blockDim.x;
    for (long long i = (long long)blockIdx.x * blockDim.x + threadIdx.x;
         i < total4; i += stride) {
        long long node = i >> 4;
        int c4         = (int)(i & 15);
        float di = g_dinv[node];
        float sl = di * di;
        float4 hv = reinterpret_cast<const float4*>(h)[i];
        float4 av = reinterpret_cast<float4*>(agg)[i];
        float4 bv = reinterpret_cast<const float4*>(b)[c4];
        av.x = fmaxf(fmaf(hv.x, sl, av.x) + bv.x, 0.f);
        av.y = fmaxf(fmaf(hv.y, sl, av.y) + bv.y, 0.f);
        av.z = fmaxf(fmaf(hv.z, sl, av.z) + bv.z, 0.f);
        av.w = fmaxf(fmaf(hv.w, sl, av.w) + bv.w, 0.f);
        reinterpret_cast<float4*>(agg)[i] = av;
    }
}

// ---------------------------------------------------------------------------
extern "C" void kernel_launch(void* const* d_in, const int* in_sizes, int n_in,
                              void* d_out, int out_size)
{
    const float* x  = (const float*)d_in[0];
    const int*   ei = (const int*)d_in[1];     // int32 (JAX x64 disabled)
    const float* W1 = (const float*)d_in[2];
    const float* b1 = (const float*)d_in[3];
    const float* W2 = (const float*)d_in[4];
    const float* b2 = (const float*)d_in[5];
    float* out = (float*)d_out;

    const long long E = (long long)in_sizes[1] / 2;

    float* g_h_ptr;   cudaGetSymbolAddress((void**)&g_h_ptr,   g_h);
    float* g_agg_ptr; cudaGetSymbolAddress((void**)&g_agg_ptr, g_agg);

    const int SMS = 148;
    dim3 blk(256);

    const int GEMM_SMEM = (64 * 64 + 128 * 65) * 4;  // 49664 B
    static bool attr_done = false;
    if (!attr_done) {
        cudaFuncSetAttribute(gemm64_kernel<false>,
            cudaFuncAttributeMaxDynamicSharedMemorySize, GEMM_SMEM);
        cudaFuncSetAttribute(gemm64_kernel<true>,
            cudaFuncAttributeMaxDynamicSharedMemorySize, GEMM_SMEM);
        attr_done = true;
    }

    // zero agg, deg, and out (out doubles as layer-2 agg buffer)
    zero_kernel<<<SMS * 8, blk>>>(out);

    // degree + normalization
    deg_kernel<<<SMS * 8, blk>>>(ei, E);
    dinv_kernel<<<(NNODES + 255) / 256, blk>>>();

    const int gemm_grid = (NNODES + 127) / 128;
    const int scat_grid = SMS * 20;

    // ---- layer 1 ----
    gemm64_kernel<false><<<gemm_grid, blk, GEMM_SMEM>>>(
        x, W1, g_h_ptr, NNODES, nullptr, nullptr);
    scatter_kernel<<<scat_grid, blk>>>(ei, E, g_h_ptr, g_agg_ptr);

    // ---- layer 2 (finalize-1 fused into A-tile load; h2 overwrites g_h) ----
    gemm64_kernel<true><<<gemm_grid, blk, GEMM_SMEM>>>(
        g_agg_ptr, W2, g_h_ptr, NNODES, g_h_ptr, b1);
    scatter_kernel<<<scat_grid, blk>>>(ei, E, g_h_ptr, out);
    finalize_kernel<<<SMS * 8, blk>>>(g_h_ptr, out, b2);
}

// round 4
// speedup vs baseline: 1.3540x; 1.0780x over previous
#include <cuda_runtime.h>
#include <cuda_bf16.h>
#include <stdint.h>

#define NNODES 100000
#define FDIM   64

// Scratch (static device globals — no allocation allowed in kernel_launch)
__device__ __align__(16) float g_h[(size_t)NNODES * FDIM];    // 25.6 MB
__device__ __align__(16) float g_agg[(size_t)NNODES * FDIM];  // 25.6 MB
__device__ float g_deg[NNODES];
__device__ float g_dinv[NNODES];

// ---------------------------------------------------------------------------
__device__ __forceinline__ void red_add_v4(float* addr, float4 v) {
    asm volatile("red.global.add.v4.f32 [%0], {%1, %2, %3, %4};"
                 :: "l"(addr), "f"(v.x), "f"(v.y), "f"(v.z), "f"(v.w)
                 : "memory");
}

// ---------------------------------------------------------------------------
// zero scratch: g_agg, g_deg, and d_out (layer-2 agg buffer)
// ---------------------------------------------------------------------------
__global__ void zero_kernel(float* __restrict__ out) {
    const long long total4 = (long long)NNODES * FDIM / 4;
    long long stride = (long long)gridDim.x * blockDim.x;
    float4 z = make_float4(0.f, 0.f, 0.f, 0.f);
    for (long long i = (long long)blockIdx.x * blockDim.x + threadIdx.x;
         i < total4; i += stride) {
        reinterpret_cast<float4*>(g_agg)[i] = z;
        reinterpret_cast<float4*>(out)[i]   = z;
    }
    for (long long i = (long long)blockIdx.x * blockDim.x + threadIdx.x;
         i < NNODES; i += stride) {
        g_deg[i] = 0.0f;
    }
}

// ---------------------------------------------------------------------------
// degree: deg[dst] += 1 per edge (exact in fp32). edge_index int32, [2, E].
// ---------------------------------------------------------------------------
__global__ void deg_kernel(const int* __restrict__ ei, long long E) {
    long long stride = (long long)gridDim.x * blockDim.x;
    for (long long e = (long long)blockIdx.x * blockDim.x + threadIdx.x;
         e < E; e += stride) {
        atomicAdd(&g_deg[ei[E + e]], 1.0f);
    }
}

__global__ void dinv_kernel() {
    long long stride = (long long)gridDim.x * blockDim.x;
    for (long long i = (long long)blockIdx.x * blockDim.x + threadIdx.x;
         i < NNODES; i += stride) {
        g_dinv[i] = rsqrtf(g_deg[i] + 1.0f);
    }
}

// ---------------------------------------------------------------------------
// GEMM: C[n,64] = A[n,64] @ W[64,64], fp32.
// 256 threads / 256 rows per block. Each thread: 4 rows x 16 cols (64 acc).
// Per 4-k step: 4 LDS.128 (A as float4 over k) + 16 LDS.128 (W, broadcast)
// vs 256 FFMA -> decisively FFMA-issue bound.
// FUSED: A-element = relu(A + hprev*dinv^2 + bias)  (fuses layer-1 finalize).
// ---------------------------------------------------------------------------
#define ROWS_PER_BLK 256
#define A_STRIDE4    17            // float4 stride per row (68 floats)

template <bool FUSED>
__global__ __launch_bounds__(256) void gemm64_kernel(
    const float* __restrict__ A, const float* __restrict__ W,
    float* __restrict__ C, int n_rows,
    const float* __restrict__ hprev, const float* __restrict__ bias)
{
    extern __shared__ float smem[];
    float*  sW  = smem;                          // 64*64 = 4096 floats
    float4* sA4 = reinterpret_cast<float4*>(smem + 64 * 64); // 256*17 float4

    const int tid  = threadIdx.x;
    const int row0 = blockIdx.x * ROWS_PER_BLK;

    // W: 64x64, coalesced float4
    for (int i = tid; i < 1024; i += 256)
        reinterpret_cast<float4*>(sW)[i] =
            reinterpret_cast<const float4*>(W)[i];

    // A tile: 256 rows x 16 float4 (optionally fused activation)
    for (int i = tid; i < ROWS_PER_BLK * 16; i += 256) {
        int r  = i >> 4;
        int c4 = i & 15;
        int row = row0 + r;
        float4 v = make_float4(0.f, 0.f, 0.f, 0.f);
        if (row < n_rows) {
            v = reinterpret_cast<const float4*>(A + (size_t)row * FDIM)[c4];
            if (FUSED) {
                float4 hv = reinterpret_cast<const float4*>(
                                hprev + (size_t)row * FDIM)[c4];
                float4 bv = reinterpret_cast<const float4*>(bias)[c4];
                float di = g_dinv[row];
                float sl = di * di;
                v.x = fmaxf(fmaf(hv.x, sl, v.x) + bv.x, 0.f);
                v.y = fmaxf(fmaf(hv.y, sl, v.y) + bv.y, 0.f);
                v.z = fmaxf(fmaf(hv.z, sl, v.z) + bv.z, 0.f);
                v.w = fmaxf(fmaf(hv.w, sl, v.w) + bv.w, 0.f);
            }
        }
        sA4[r * A_STRIDE4 + c4] = v;
    }
    __syncthreads();

    const int rbase = (tid >> 2) * 4;   // local row base: 0..252 step 4
    const int cg    = (tid & 3) * 16;   // col base: 0/16/32/48

    float acc[4][16];
#pragma unroll
    for (int r = 0; r < 4; r++)
#pragma unroll
        for (int i = 0; i < 16; i++) acc[r][i] = 0.f;

#pragma unroll
    for (int k4 = 0; k4 < 16; k4++) {
        float4 a[4];
#pragma unroll
        for (int r = 0; r < 4; r++)
            a[r] = sA4[(rbase + r) * A_STRIDE4 + k4];

#pragma unroll
        for (int kk = 0; kk < 4; kk++) {
            const float4* wr = reinterpret_cast<const float4*>(
                sW + (k4 * 4 + kk) * 64 + cg);
            float4 w0 = wr[0], w1 = wr[1], w2 = wr[2], w3 = wr[3];
#pragma unroll
            for (int r = 0; r < 4; r++) {
                float av = (&a[r].x)[kk];
                acc[r][0]  = fmaf(av, w0.x, acc[r][0]);
                acc[r][1]  = fmaf(av, w0.y, acc[r][1]);
                acc[r][2]  = fmaf(av, w0.z, acc[r][2]);
                acc[r][3]  = fmaf(av, w0.w, acc[r][3]);
                acc[r][4]  = fmaf(av, w1.x, acc[r][4]);
                acc[r][5]  = fmaf(av, w1.y, acc[r][5]);
                acc[r][6]  = fmaf(av, w1.z, acc[r][6]);
                acc[r][7]  = fmaf(av, w1.w, acc[r][7]);
                acc[r][8]  = fmaf(av, w2.x, acc[r][8]);
                acc[r][9]  = fmaf(av, w2.y, acc[r][9]);
                acc[r][10] = fmaf(av, w2.z, acc[r][10]);
                acc[r][11] = fmaf(av, w2.w, acc[r][11]);
                acc[r][12] = fmaf(av, w3.x, acc[r][12]);
                acc[r][13] = fmaf(av, w3.y, acc[r][13]);
                acc[r][14] = fmaf(av, w3.z, acc[r][14]);
                acc[r][15] = fmaf(av, w3.w, acc[r][15]);
            }
        }
    }

#pragma unroll
    for (int r = 0; r < 4; r++) {
        int row = row0 + rbase + r;
        if (row < n_rows) {
            float4* o = reinterpret_cast<float4*>(
                C + (size_t)row * FDIM + cg);
#pragma unroll
            for (int i = 0; i < 4; i++)
                o[i] = make_float4(acc[r][4*i+0], acc[r][4*i+1],
                                   acc[r][4*i+2], acc[r][4*i+3]);
        }
    }
}

// ---------------------------------------------------------------------------
// Edge scatter: agg[dst] += h[src] * dinv[src] * dinv[dst]
// 16 lanes per edge, each lane owns one float4 of the 64-float row.
// ---------------------------------------------------------------------------
__global__ __launch_bounds__(256) void scatter_kernel(
    const int* __restrict__ ei, long long E,
    const float* __restrict__ h, float* __restrict__ agg)
{
    const long long nlane = E * 16;
    const long long stride = (long long)gridDim.x * blockDim.x;
    for (long long i = (long long)blockIdx.x * blockDim.x + threadIdx.x;
         i < nlane; i += stride) {
        long long e = i >> 4;
        int sub     = (int)(i & 15);
        long long s = ei[e];
        long long d = ei[E + e];
        float norm  = g_dinv[s] * g_dinv[d];
        float4 v = reinterpret_cast<const float4*>(h + s * FDIM)[sub];
        v.x *= norm; v.y *= norm; v.z *= norm; v.w *= norm;
        red_add_v4(agg + d * FDIM + sub * 4, v);
    }
}

// ---------------------------------------------------------------------------
// Finalize: agg = relu(agg + h * dinv^2 + b)   (in place on agg)
// ---------------------------------------------------------------------------
__global__ __launch_bounds__(256) void finalize_kernel(
    const float* __restrict__ h, float* __restrict__ agg,
    const float* __restrict__ b)
{
    const long long total4 = (long long)NNODES * (FDIM / 4);
    const long long stride = (long long)gridDim.x * blockDim.x;
    for (long long i = (long long)blockIdx.x * blockDim.x + threadIdx.x;
         i < total4; i += stride) {
        long long node = i >> 4;
        int c4         = (int)(i & 15);
        float di = g_dinv[node];
        float sl = di * di;
        float4 hv = reinterpret_cast<const float4*>(h)[i];
        float4 av = reinterpret_cast<float4*>(agg)[i];
        float4 bv = reinterpret_cast<const float4*>(b)[c4];
        av.x = fmaxf(fmaf(hv.x, sl, av.x) + bv.x, 0.f);
        av.y = fmaxf(fmaf(hv.y, sl, av.y) + bv.y, 0.f);
        av.z = fmaxf(fmaf(hv.z, sl, av.z) + bv.z, 0.f);
        av.w = fmaxf(fmaf(hv.w, sl, av.w) + bv.w, 0.f);
        reinterpret_cast<float4*>(agg)[i] = av;
    }
}

// ---------------------------------------------------------------------------
extern "C" void kernel_launch(void* const* d_in, const int* in_sizes, int n_in,
                              void* d_out, int out_size)
{
    const float* x  = (const float*)d_in[0];
    const int*   ei = (const int*)d_in[1];     // int32 (JAX x64 disabled)
    const float* W1 = (const float*)d_in[2];
    const float* b1 = (const float*)d_in[3];
    const float* W2 = (const float*)d_in[4];
    const float* b2 = (const float*)d_in[5];
    float* out = (float*)d_out;

    const long long E = (long long)in_sizes[1] / 2;

    float* g_h_ptr;   cudaGetSymbolAddress((void**)&g_h_ptr,   g_h);
    float* g_agg_ptr; cudaGetSymbolAddress((void**)&g_agg_ptr, g_agg);

    const int SMS = 148;
    dim3 blk(256);

    const int GEMM_SMEM = (64 * 64 + ROWS_PER_BLK * A_STRIDE4 * 4) * 4; // 84 KB
    static bool attr_done = false;
    if (!attr_done) {
        cudaFuncSetAttribute(gemm64_kernel<false>,
            cudaFuncAttributeMaxDynamicSharedMemorySize, GEMM_SMEM);
        cudaFuncSetAttribute(gemm64_kernel<true>,
            cudaFuncAttributeMaxDynamicSharedMemorySize, GEMM_SMEM);
        attr_done = true;
    }

    // zero agg, deg, and out (out doubles as layer-2 agg buffer)
    zero_kernel<<<SMS * 8, blk>>>(out);

    // degree + normalization
    deg_kernel<<<SMS * 8, blk>>>(ei, E);
    dinv_kernel<<<(NNODES + 255) / 256, blk>>>();

    const int gemm_grid = (NNODES + ROWS_PER_BLK - 1) / ROWS_PER_BLK;
    const int scat_grid = SMS * 20;

    // ---- layer 1 ----
    gemm64_kernel<false><<<gemm_grid, blk, GEMM_SMEM>>>(
        x, W1, g_h_ptr, NNODES, nullptr, nullptr);
    scatter_kernel<<<scat_grid, blk>>>(ei, E, g_h_ptr, g_agg_ptr);

    // ---- layer 2 (finalize-1 fused into A-tile load; h2 overwrites g_h) ----
    gemm64_kernel<true><<<gemm_grid, blk, GEMM_SMEM>>>(
        g_agg_ptr, W2, g_h_ptr, NNODES, g_h_ptr, b1);
    scatter_kernel<<<scat_grid, blk>>>(ei, E, g_h_ptr, out);
    finalize_kernel<<<SMS * 8, blk>>>(g_h_ptr, out, b2);
}